// round 17
// baseline (speedup 1.0000x reference)
#include <cuda_runtime.h>
#include <cstddef>

// GraphConvS: out[b,i,f] = sum_j adj[b,i,j] * (concat(sf1,sf2)[b,i,j,:] . W[:,f] + bias[f])
//           = (sum_{j: adj=1} x[b,i,j,:]) . W + deg[b,i] * bias      (adjacency is binary)
//
// One warp per (b,i) row (R9 shape: best measured). Ballot+popc compaction into
// a SLOT-MAJOR shared list (slot g's entries contiguous -> one LDS.32 per 4
// gather iterations). Gather: 4 neighbor-slots x 8 lanes, float4 per lane
// (8 lanes * 16B = full 128B feature row), unroll 8 so the whole list issues
// as one load burst. Epilogue GEMV vs W transposed in shared.

static constexpr int Bdim    = 64;
static constexpr int Mdim    = 128;
static constexpr int Fhalf   = 32;
static constexpr int FILTERS = 32;
static constexpr int WARPS_PER_CTA = 8;
static constexpr int ROWS = Bdim * Mdim;  // 8192
static constexpr int WT_STRIDE = 68;      // 68 % 32 == 4 -> LDS.128 phase-conflict-free

__global__ void __launch_bounds__(WARPS_PER_CTA * 32)
graphconvs_kernel(const float* __restrict__ sf1,
                  const float* __restrict__ sf2,
                  const float* __restrict__ adj,
                  const float* __restrict__ W,     // [64, 32] row-major (k, f)
                  const float* __restrict__ bias,  // [32]
                  float* __restrict__ out)         // [B*M, 32]
{
    __shared__ float    WTs[FILTERS][WT_STRIDE];        // WT[f][k] = W[k][f]
    __shared__ float    sacc[WARPS_PER_CTA][64];
    __shared__ unsigned jl[WARPS_PER_CTA][32];          // slot-major neighbor ids (bytes)

    const int tid  = threadIdx.x;
    const int warp = tid >> 5;
    const int lane = tid & 31;
    const int row  = blockIdx.x * WARPS_PER_CTA + warp;   // b*M + i  (< 8192)

    // issue early: bias + adjacency row (independent loads in flight)
    const float  bl = __ldg(&bias[lane]);
    const float4 av = __ldg((const float4*)(adj + (size_t)row * Mdim) + lane);

    // ---- stage W transposed into shared (float4 loads, scatter stores) ----
    {
        const float4* W4 = (const float4*)W;   // 512 float4's
        #pragma unroll
        for (int q = 0; q < 2; ++q) {
            const int idx = tid + q * 256;     // float4 index
            const float4 w = __ldg(&W4[idx]);
            const int k = idx >> 3;            // (idx*4) / 32
            const int f = (idx & 7) * 4;
            WTs[f + 0][k] = w.x;  WTs[f + 1][k] = w.y;
            WTs[f + 2][k] = w.z;  WTs[f + 3][k] = w.w;
        }
    }

    // ---- compaction: rank r stored slot-major at byte (r&3)*32 + (r>>2) ----
    const unsigned FULL = 0xffffffffu;
    const unsigned lt = (1u << lane) - 1u;

    const unsigned b0 = __ballot_sync(FULL, av.x != 0.0f);
    const unsigned b1 = __ballot_sync(FULL, av.y != 0.0f);
    const unsigned b2 = __ballot_sync(FULL, av.z != 0.0f);
    const unsigned b3 = __ballot_sync(FULL, av.w != 0.0f);
    const int c0 = __popc(b0);
    const int c1 = c0 + __popc(b1);
    const int c2 = c1 + __popc(b2);
    const int total = c2 + __popc(b3);

    unsigned char* jlw = (unsigned char*)jl[warp];
    {
        int r;
        if (av.x != 0.0f) { r =      __popc(b0 & lt); jlw[(r & 3) * 32 + (r >> 2)] = (unsigned char)(4 * lane + 0); }
        if (av.y != 0.0f) { r = c0 + __popc(b1 & lt); jlw[(r & 3) * 32 + (r >> 2)] = (unsigned char)(4 * lane + 1); }
        if (av.z != 0.0f) { r = c1 + __popc(b2 & lt); jlw[(r & 3) * 32 + (r >> 2)] = (unsigned char)(4 * lane + 2); }
        if (av.w != 0.0f) { r = c2 + __popc(b3 & lt); jlw[(r & 3) * 32 + (r >> 2)] = (unsigned char)(4 * lane + 3); }
    }
    __syncwarp();

    const float deg = (float)total;   // adjacency is binary

    // ---- gather: slot g handles ranks r = g, g+4, ...; entry i at byte g*32+i ----
    const float4* x1 = (const float4*)(sf1 + (size_t)row * Mdim * Fhalf);
    const float4* x2 = (const float4*)(sf2 + (size_t)row * Mdim * Fhalf);
    const int g  = lane >> 3;   // neighbor slot 0..3
    const int cq = lane & 7;    // channel quad 0..7

    float4 acc1 = make_float4(0.f, 0.f, 0.f, 0.f);
    float4 acc2 = make_float4(0.f, 0.f, 0.f, 0.f);

    const unsigned* jlw32 = &jl[warp][g * 8];      // 8 uints cover up to 32 entries
    const int n = (total - g + 3) >> 2;            // iterations for this slot

    unsigned cur = 0;
    #pragma unroll 8
    for (int i = 0; i < n; ++i) {
        if ((i & 3) == 0) cur = jlw32[i >> 2];     // one LDS.32 per 4 iterations
        const int j   = (int)((cur >> ((i & 3) * 8)) & 0xffu);
        const int idx = j * 8 + cq;
        const float4 v1 = __ldg(&x1[idx]);
        const float4 v2 = __ldg(&x2[idx]);
        acc1.x += v1.x; acc1.y += v1.y; acc1.z += v1.z; acc1.w += v1.w;
        acc2.x += v2.x; acc2.y += v2.y; acc2.z += v2.z; acc2.w += v2.w;
    }

    // ---- merge the 4 neighbor-slot partials (xor 8, 16) ----
    #pragma unroll
    for (int off = 8; off <= 16; off <<= 1) {
        acc1.x += __shfl_xor_sync(FULL, acc1.x, off);
        acc1.y += __shfl_xor_sync(FULL, acc1.y, off);
        acc1.z += __shfl_xor_sync(FULL, acc1.z, off);
        acc1.w += __shfl_xor_sync(FULL, acc1.w, off);
        acc2.x += __shfl_xor_sync(FULL, acc2.x, off);
        acc2.y += __shfl_xor_sync(FULL, acc2.y, off);
        acc2.z += __shfl_xor_sync(FULL, acc2.z, off);
        acc2.w += __shfl_xor_sync(FULL, acc2.w, off);
    }
    if (lane < 8) {
        ((float4*)&sacc[warp][0])[lane]  = acc1;   // channels k = lane*4..+3
        ((float4*)&sacc[warp][32])[lane] = acc2;   // channels k = 32+lane*4..+3
    }
    __syncthreads();   // orders WTs writes (and sacc, per-warp) before reads

    // ---- epilogue GEMV: r[f] = deg*bias[f] + sum_k acc[k]*WT[f][k] ----
    float p0 = 0.f, p1 = 0.f;
    #pragma unroll
    for (int k4 = 0; k4 < 16; ++k4) {
        const float4 s = *(const float4*)&sacc[warp][k4 * 4];     // broadcast
        const float4 w = *(const float4*)&WTs[lane][k4 * 4];      // conflict-free
        p0 = fmaf(s.x, w.x, p0); p1 = fmaf(s.y, w.y, p1);
        p0 = fmaf(s.z, w.z, p0); p1 = fmaf(s.w, w.w, p1);
    }
    out[(size_t)row * FILTERS + lane] = fmaf(deg, bl, p0 + p1);
}

extern "C" void kernel_launch(void* const* d_in, const int* in_sizes, int n_in,
                              void* d_out, int out_size)
{
    // metadata order: scalar_features_1, scalar_features_2, adjacency, W, b
    const float* sf1  = (const float*)d_in[0];
    const float* sf2  = (const float*)d_in[1];
    const float* adj  = (const float*)d_in[2];
    const float* W    = (const float*)d_in[3];
    const float* bias = (const float*)d_in[4];
    float* out = (float*)d_out;

    graphconvs_kernel<<<ROWS / WARPS_PER_CTA, WARPS_PER_CTA * 32>>>(
        sf1, sf2, adj, W, bias, out);
}